// round 8
// baseline (speedup 1.0000x reference)
#include <cuda_runtime.h>
#include <math.h>

#define SS 512
#define CC 384
#define HH 12
#define NPROJ 1152   // 192 qs + 192 ks + 192 vs + 144 qp + 144 kp + 288 vp
#define AD 32        // augmented logit dim (30 used, padded to 32)
#define VD 40        // 16 scalar + 8 points * 3
#define COMB 576     // 192 scalar_out + 288 pol + 96 norms

// ---------------- scratch (device globals; no allocation allowed) ----------
__device__ float g_Wc[CC * NPROJ];
__device__ float g_bc[NPROJ];
__device__ float g_proj[SS * NPROJ];
__device__ float g_Qa[HH * AD * SS];     // dim-major augmented Q
__device__ float g_Ka[HH * AD * SS];     // dim-major augmented K
__device__ float g_Vc[HH * SS * VD];
__device__ float g_attn[HH * SS * SS];
__device__ float g_comb[SS * COMB];
__device__ float g_maskf[SS];
__device__ float g_spw[HH * 4];          // softplus(point_weights)

// ---------------- K0: pack weights (float4 segment copies) + mask + softplus
__global__ void pack_weights(const float* __restrict__ Wq_s, const float* __restrict__ Wk_s,
                             const float* __restrict__ Wv_s, const float* __restrict__ Wq_p,
                             const float* __restrict__ Wk_p, const float* __restrict__ Wv_p,
                             const float* __restrict__ bq_s, const float* __restrict__ bk_s,
                             const float* __restrict__ bv_s, const float* __restrict__ bq_p,
                             const float* __restrict__ bk_p, const float* __restrict__ bv_p,
                             const float* __restrict__ pw,
                             const unsigned char* __restrict__ msk) {
    if (blockIdx.x == 0) {
        __shared__ int flag;
        int t = threadIdx.x;             // 256
        if (t == 0) flag = 0;
        __syncthreads();
        #pragma unroll
        for (int b = t; b < 512; b += 256)
            if ((b & 3) != 0 && msk[b] != 0) atomicOr(&flag, 1);
        __syncthreads();
        for (int i = t; i < SS; i += 256)
            g_maskf[i] = flag ? (msk[i] != 0 ? 1.0f : 0.0f)
                              : (((const int*)msk)[i] != 0 ? 1.0f : 0.0f);
        if (t < HH * 4) {
            float x = pw[t];
            g_spw[t] = (x > 20.0f) ? x : log1pf(expf(x));
        }
    }
    const int ROW4 = NPROJ / 4;          // 288
    const int TOT4 = CC * ROW4;          // 110592
    float4* dstW = (float4*)g_Wc;
    for (int idx = blockIdx.x * blockDim.x + threadIdx.x; idx < TOT4 + ROW4;
         idx += gridDim.x * blockDim.x) {
        if (idx < TOT4) {
            int row = idx / ROW4, r = idx % ROW4;
            const float* src;  int c4, w4;
            if      (r < 48)  { src = Wq_s; c4 = r;        w4 = 48; }
            else if (r < 96)  { src = Wk_s; c4 = r - 48;   w4 = 48; }
            else if (r < 144) { src = Wv_s; c4 = r - 96;   w4 = 48; }
            else if (r < 180) { src = Wq_p; c4 = r - 144;  w4 = 36; }
            else if (r < 216) { src = Wk_p; c4 = r - 180;  w4 = 36; }
            else              { src = Wv_p; c4 = r - 216;  w4 = 72; }
            dstW[idx] = ((const float4*)src)[row * w4 + c4];
        } else {
            int r = idx - TOT4;
            const float* src;  int c4;
            if      (r < 48)  { src = bq_s; c4 = r; }
            else if (r < 96)  { src = bk_s; c4 = r - 48; }
            else if (r < 144) { src = bv_s; c4 = r - 96; }
            else if (r < 180) { src = bq_p; c4 = r - 144; }
            else if (r < 216) { src = bk_p; c4 = r - 180; }
            else              { src = bv_p; c4 = r - 216; }
            ((float4*)g_bc)[r] = ((const float4*)src)[c4];
        }
    }
}

// ---------------- SGEMM v2: 64x64 tile, 128 threads, 8x4 microtile ---------
// C[M,N] = A[M,K] @ W[K,N] + bias, optional row mask. Double-buffered smem.
__global__ void gemm64(const float* __restrict__ A, const float* __restrict__ W,
                       const float* __restrict__ bias, float* __restrict__ Cmat,
                       int M, int N, int K, const float* __restrict__ mask) {
    __shared__ __align__(16) float As[2][16][64];
    __shared__ __align__(16) float Ws[2][16][64];
    int tid = threadIdx.x;               // 128
    int tx = tid & 15, ty = tid >> 4;    // tx: 16 col-groups of 4, ty: 8 row-groups of 8
    int n0 = blockIdx.x * 64, m0 = blockIdx.y * 64;

    int kkA[8], mA[8], nW[8], kkW[8];
    #pragma unroll
    for (int l = 0; l < 8; ++l) {
        int e = tid + l * 128;
        kkA[l] = e & 15;  mA[l] = e >> 4;
        nW[l]  = e & 63;  kkW[l] = e >> 6;
    }
    #pragma unroll
    for (int l = 0; l < 8; ++l) {
        As[0][kkA[l]][mA[l]] = A[(m0 + mA[l]) * K + kkA[l]];
        Ws[0][kkW[l]][nW[l]] = W[kkW[l] * N + n0 + nW[l]];
    }
    __syncthreads();

    float acc[8][4] = {};
    int nt = K >> 4;
    for (int t = 0; t < nt; ++t) {
        int cur = t & 1;
        float ar[8], wr[8];
        if (t + 1 < nt) {
            int k0n = (t + 1) << 4;
            #pragma unroll
            for (int l = 0; l < 8; ++l) {
                ar[l] = A[(m0 + mA[l]) * K + k0n + kkA[l]];
                wr[l] = W[(k0n + kkW[l]) * N + n0 + nW[l]];
            }
        }
        #pragma unroll
        for (int kk = 0; kk < 16; ++kk) {
            float4 a0 = *(const float4*)&As[cur][kk][ty * 8];
            float4 a1 = *(const float4*)&As[cur][kk][ty * 8 + 4];
            float4 b4 = *(const float4*)&Ws[cur][kk][tx * 4];
            float av[8] = {a0.x, a0.y, a0.z, a0.w, a1.x, a1.y, a1.z, a1.w};
            float bv[4] = {b4.x, b4.y, b4.z, b4.w};
            #pragma unroll
            for (int i = 0; i < 8; ++i)
                #pragma unroll
                for (int j = 0; j < 4; ++j) acc[i][j] += av[i] * bv[j];
        }
        if (t + 1 < nt) {
            #pragma unroll
            for (int l = 0; l < 8; ++l) {
                As[cur ^ 1][kkA[l]][mA[l]] = ar[l];
                Ws[cur ^ 1][kkW[l]][nW[l]] = wr[l];
            }
        }
        __syncthreads();
    }
    float4 b4 = *(const float4*)&bias[n0 + tx * 4];
    #pragma unroll
    for (int i = 0; i < 8; ++i) {
        int m = m0 + ty * 8 + i;
        float sc = mask ? mask[m] : 1.0f;
        float4 v;
        v.x = (acc[i][0] + b4.x) * sc;
        v.y = (acc[i][1] + b4.y) * sc;
        v.z = (acc[i][2] + b4.z) * sc;
        v.w = (acc[i][3] + b4.w) * sc;
        *(float4*)&Cmat[m * N + n0 + tx * 4] = v;
    }
}

// ---------------- K2: rotate points, build augmented Q̃/K̃ (dim-major) + V --
__global__ void rotate_pack(const float* __restrict__ rot, const float* __restrict__ trans) {
    int s = blockIdx.x;
    int t = threadIdx.x;                 // 128 threads
    __shared__ float pts[576];
    __shared__ float Rs[9], ts_[3];
    if (t < 9) Rs[t] = rot[s * 9 + t];
    if (t >= 16 && t < 19) ts_[t - 16] = trans[s * 3 + (t - 16)];
    const float* pr = g_proj + s * NPROJ;

    #pragma unroll
    for (int e = t; e < 576; e += 128) {
        float v = pr[e];
        int seg = e / 192, r = e % 192;
        int h = r >> 4, d = r & 15;
        if      (seg == 0) g_Qa[h * (AD * SS) + d * SS + s] = 0.25f * v;
        else if (seg == 1) g_Ka[h * (AD * SS) + d * SS + s] = v;
        else               g_Vc[(h * SS + s) * VD + d] = v;
    }
    #pragma unroll
    for (int e = t; e < 576; e += 128) pts[e] = pr[576 + e];
    __syncthreads();

    if (t < 24) {
        bool isQ = t < 12;
        int h = isQ ? t : t - 12;
        const float* p = pts + (isQ ? 0 : 144) + h * 12;
        float* base = (isQ ? g_Qa : g_Ka) + h * (AD * SS);
        float s2 = 0.0f;
        #pragma unroll
        for (int pp = 0; pp < 4; ++pp) {
            float x = p[pp * 3 + 0], y = p[pp * 3 + 1], z = p[pp * 3 + 2];
            float gx = Rs[0] * x + Rs[1] * y + Rs[2] * z + ts_[0];
            float gy = Rs[3] * x + Rs[4] * y + Rs[5] * z + ts_[1];
            float gz = Rs[6] * x + Rs[7] * y + Rs[8] * z + ts_[2];
            float w = g_spw[h * 4 + pp];
            s2 += w * (gx * gx + gy * gy + gz * gz);
            float m = isQ ? w : 1.0f;
            base[(16 + pp * 3 + 0) * SS + s] = m * gx;
            base[(16 + pp * 3 + 1) * SS + s] = m * gy;
            base[(16 + pp * 3 + 2) * SS + s] = m * gz;
        }
        base[28 * SS + s] = isQ ? -0.5f * s2 : 1.0f;
        base[29 * SS + s] = isQ ? 1.0f : -0.5f * s2;
        base[30 * SS + s] = 0.0f;
        base[31 * SS + s] = 0.0f;
    } else if (t >= 32) {
        int q = t - 32;                   // 96 v-point tasks
        const float* p = pts + 288 + q * 3;
        float* o = g_Vc + ((q >> 3) * SS + s) * VD + 16 + (q & 7) * 3;
        float x = p[0], y = p[1], z = p[2];
        o[0] = Rs[0] * x + Rs[1] * y + Rs[2] * z + ts_[0];
        o[1] = Rs[3] * x + Rs[4] * y + Rs[5] * z + ts_[1];
        o[2] = Rs[6] * x + Rs[7] * y + Rs[8] * z + ts_[2];
    }
}

// ---------------- K3a: logits[h] = Q̃ᵀ K̃ ; tile 64m x 128n, 8x4 microtile --
__global__ void logits_gemm() {
    int h = blockIdx.z;
    int n0 = blockIdx.x * 128, m0 = blockIdx.y * 64;
    __shared__ __align__(16) float Qs[AD][64];
    __shared__ __align__(16) float Ks[AD][128];
    int tid = threadIdx.x;               // 256
    const float* qb = g_Qa + h * (AD * SS);
    const float* kb = g_Ka + h * (AD * SS);
    #pragma unroll
    for (int l = 0; l < 2; ++l) {
        int idx = tid + l * 256;         // 512 float4 slots for Qs
        int k = idx >> 4, m4 = idx & 15;
        *(float4*)&Qs[k][m4 * 4] = *(const float4*)&qb[k * SS + m0 + m4 * 4];
    }
    #pragma unroll
    for (int l = 0; l < 4; ++l) {
        int idx = tid + l * 256;         // 1024 float4 slots for Ks
        int k = idx >> 5, n4 = idx & 31;
        *(float4*)&Ks[k][n4 * 4] = *(const float4*)&kb[k * SS + n0 + n4 * 4];
    }
    __syncthreads();
    int tx = tid & 31, ty = tid >> 5;    // tx: 32 col-groups, ty: 8 row-groups
    float acc[8][4] = {};
    #pragma unroll
    for (int k = 0; k < AD; ++k) {
        float4 b4 = *(const float4*)&Ks[k][tx * 4];
        float4 a0 = *(const float4*)&Qs[k][ty * 8];
        float4 a1 = *(const float4*)&Qs[k][ty * 8 + 4];
        float av[8] = {a0.x, a0.y, a0.z, a0.w, a1.x, a1.y, a1.z, a1.w};
        float bv[4] = {b4.x, b4.y, b4.z, b4.w};
        #pragma unroll
        for (int i = 0; i < 8; ++i)
            #pragma unroll
            for (int j = 0; j < 4; ++j) acc[i][j] += av[i] * bv[j];
    }
    float4 mq = ((const float4*)g_maskf)[(n0 >> 2) + tx];
    #pragma unroll
    for (int i = 0; i < 8; ++i) {
        int m = m0 + ty * 8 + i;
        float4 v;
        v.x = (mq.x != 0.0f) ? acc[i][0] : -10000.0f;
        v.y = (mq.y != 0.0f) ? acc[i][1] : -10000.0f;
        v.z = (mq.z != 0.0f) ? acc[i][2] : -10000.0f;
        v.w = (mq.w != 0.0f) ? acc[i][3] : -10000.0f;
        *(float4*)&g_attn[(h * SS + m) * SS + n0 + tx * 4] = v;
    }
}

// ---------------- K3b: softmax over rows of g_attn (warp per row) ----------
__global__ void softmax_rows() {
    int row = blockIdx.x * 8 + (threadIdx.x >> 5);   // 0 .. HH*SS-1
    int lane = threadIdx.x & 31;
    float* r = g_attn + row * SS;
    float4 v[4];
    float m = -1e30f;
    #pragma unroll
    for (int c = 0; c < 4; ++c) {
        v[c] = *(const float4*)&r[(lane + c * 32) * 4];
        m = fmaxf(m, fmaxf(fmaxf(v[c].x, v[c].y), fmaxf(v[c].z, v[c].w)));
    }
    #pragma unroll
    for (int o = 16; o; o >>= 1) m = fmaxf(m, __shfl_xor_sync(0xFFFFFFFFu, m, o));
    float sum = 0.0f;
    #pragma unroll
    for (int c = 0; c < 4; ++c) {
        v[c].x = __expf(v[c].x - m);  v[c].y = __expf(v[c].y - m);
        v[c].z = __expf(v[c].z - m);  v[c].w = __expf(v[c].w - m);
        sum += v[c].x + v[c].y + v[c].z + v[c].w;
    }
    #pragma unroll
    for (int o = 16; o; o >>= 1) sum += __shfl_xor_sync(0xFFFFFFFFu, sum, o);
    float inv = g_maskf[row & (SS - 1)] / sum;
    #pragma unroll
    for (int c = 0; c < 4; ++c) {
        v[c].x *= inv;  v[c].y *= inv;  v[c].z *= inv;  v[c].w *= inv;
        *(float4*)&r[(lane + c * 32) * 4] = v[c];
    }
}

// ---------------- K4: attn@V fused with combined-feature epilogue ----------
__global__ void attn_apply(const float* __restrict__ rot, const float* __restrict__ trans) {
    int h = blockIdx.y, i0 = blockIdx.x * 32;
    __shared__ __align__(16) float at[32][68];   // padded
    __shared__ __align__(16) float vv[64][VD];
    __shared__ __align__(16) float ot[32][44];   // out40 staging (padded)
    int tid = threadIdx.x;
    int il = tid >> 3, dg = tid & 7;   // 32 queries x 8 dim-groups (5 dims each)
    float acc[5] = {};
    for (int j0 = 0; j0 < SS; j0 += 64) {
        #pragma unroll
        for (int l = 0; l < 2; ++l) {            // 512 float4 fills of at
            int idx = tid + l * 256;
            int rr = idx >> 4, c4 = idx & 15;
            *(float4*)&at[rr][c4 * 4] =
                *(const float4*)&g_attn[(h * SS + i0 + rr) * SS + j0 + c4 * 4];
        }
        #pragma unroll
        for (int l = 0; l < 3; ++l) {            // 640 float4 fills of vv
            int idx = tid + l * 256;
            if (idx < 640) {
                int rr = idx / 10, c4 = idx % 10;
                *(float4*)&vv[rr][c4 * 4] =
                    ((const float4*)(g_Vc + (h * SS + j0 + rr) * VD))[c4];
            }
        }
        __syncthreads();
        #pragma unroll 8
        for (int jj = 0; jj < 64; ++jj) {
            float a = at[il][jj];
            #pragma unroll
            for (int q = 0; q < 5; ++q) acc[q] += a * vv[jj][dg * 5 + q];
        }
        __syncthreads();
    }
    #pragma unroll
    for (int q = 0; q < 5; ++q) ot[il][dg * 5 + q] = acc[q];
    __syncthreads();

    // epilogue: scalar copies (512 tasks -> 2 per thread)
    #pragma unroll
    for (int l = 0; l < 2; ++l) {
        int e = tid + l * 256;
        int q = e >> 4, d = e & 15;              // query, scalar dim
        g_comb[(i0 + q) * COMB + h * 16 + d] = ot[q][d];
    }
    // epilogue: point tasks (32 queries x 8 points = 256, one per thread)
    {
        int q = tid >> 3, p = tid & 7;
        int s = i0 + q;
        float v0 = ot[q][16 + 3 * p + 0] - trans[s * 3 + 0];
        float v1 = ot[q][16 + 3 * p + 1] - trans[s * 3 + 1];
        float v2 = ot[q][16 + 3 * p + 2] - trans[s * 3 + 2];
        const float* R = rot + s * 9;
        float p0 = R[0] * v0 + R[3] * v1 + R[6] * v2;   // R^T v
        float p1 = R[1] * v0 + R[4] * v1 + R[7] * v2;
        float p2 = R[2] * v0 + R[5] * v1 + R[8] * v2;
        float* cb = g_comb + s * COMB;
        cb[192 + (h * 8 + p) * 3 + 0] = p0;
        cb[192 + (h * 8 + p) * 3 + 1] = p1;
        cb[192 + (h * 8 + p) * 3 + 2] = p2;
        cb[480 + h * 8 + p] = sqrtf(p0 * p0 + p1 * p1 + p2 * p2);
    }
}

// ---------------------------------------------------------------------------
extern "C" void kernel_launch(void* const* d_in, const int* in_sizes, int n_in,
                              void* d_out, int out_size) {
    const float* single = (const float*)d_in[0];
    const float* rot    = (const float*)d_in[1];
    const float* trans  = (const float*)d_in[2];
    const float* Wq_s = (const float*)d_in[3];  const float* bq_s = (const float*)d_in[4];
    const float* Wk_s = (const float*)d_in[5];  const float* bk_s = (const float*)d_in[6];
    const float* Wv_s = (const float*)d_in[7];  const float* bv_s = (const float*)d_in[8];
    const float* Wq_p = (const float*)d_in[9];  const float* bq_p = (const float*)d_in[10];
    const float* Wk_p = (const float*)d_in[11]; const float* bk_p = (const float*)d_in[12];
    const float* Wv_p = (const float*)d_in[13]; const float* bv_p = (const float*)d_in[14];
    const float* pw   = (const float*)d_in[15];
    const float* Wo   = (const float*)d_in[16];
    const float* bo   = (const float*)d_in[17];
    const unsigned char* mask = (const unsigned char*)d_in[18];
    float* out = (float*)d_out;

    float *pWc, *pbc, *pproj, *pcomb, *pmaskf;
    cudaGetSymbolAddress((void**)&pWc,    g_Wc);
    cudaGetSymbolAddress((void**)&pbc,    g_bc);
    cudaGetSymbolAddress((void**)&pproj,  g_proj);
    cudaGetSymbolAddress((void**)&pcomb,  g_comb);
    cudaGetSymbolAddress((void**)&pmaskf, g_maskf);

    pack_weights<<<432, 256>>>(Wq_s, Wk_s, Wv_s, Wq_p, Wk_p, Wv_p,
                               bq_s, bk_s, bv_s, bq_p, bk_p, bv_p, pw, mask);
    gemm64<<<dim3(NPROJ / 64, SS / 64), 128>>>(single, pWc, pbc, pproj,
                                               SS, NPROJ, CC, (const float*)0);
    rotate_pack<<<SS, 128>>>(rot, trans);
    logits_gemm<<<dim3(SS / 128, SS / 64, HH), 256>>>();
    softmax_rows<<<HH * SS / 8, 256>>>();
    attn_apply<<<dim3(SS / 32, HH), 256>>>(rot, trans);
    gemm64<<<dim3(CC / 64, SS / 64), 128>>>(pcomb, Wo, bo, out, SS, CC, COMB, pmaskf);
}

// round 9
// speedup vs baseline: 1.0920x; 1.0920x over previous
#include <cuda_runtime.h>
#include <math.h>

#define SS 512
#define CC 384
#define HH 12
#define NPROJ 1152   // 192 qs + 192 ks + 192 vs + 144 qp + 144 kp + 288 vp
#define AD 32        // augmented logit dim (30 used, padded to 32)
#define VD 40        // 16 scalar + 8 points * 3
#define COMB 576     // 192 scalar_out + 288 pol + 96 norms

// ---------------- scratch (device globals; no allocation allowed) ----------
__device__ float g_Wc[CC * NPROJ];
__device__ float g_bc[NPROJ];
__device__ float g_proj[SS * NPROJ];
__device__ float g_Qa[HH * AD * SS];     // dim-major augmented Q
__device__ float g_Ka[HH * AD * SS];     // dim-major augmented K
__device__ float g_Vc[HH * SS * VD];
__device__ float g_attn[HH * SS * SS];
__device__ float g_comb[SS * COMB];
__device__ float g_maskf[SS];
__device__ float g_spw[HH * 4];          // softplus(point_weights)

// ---------------- K0: pack weights (float4 segment copies) + mask + softplus
__global__ void pack_weights(const float* __restrict__ Wq_s, const float* __restrict__ Wk_s,
                             const float* __restrict__ Wv_s, const float* __restrict__ Wq_p,
                             const float* __restrict__ Wk_p, const float* __restrict__ Wv_p,
                             const float* __restrict__ bq_s, const float* __restrict__ bk_s,
                             const float* __restrict__ bv_s, const float* __restrict__ bq_p,
                             const float* __restrict__ bk_p, const float* __restrict__ bv_p,
                             const float* __restrict__ pw,
                             const unsigned char* __restrict__ msk) {
    if (blockIdx.x == 0) {
        __shared__ int flag;
        int t = threadIdx.x;             // 256
        if (t == 0) flag = 0;
        __syncthreads();
        #pragma unroll
        for (int b = t; b < 512; b += 256)
            if ((b & 3) != 0 && msk[b] != 0) atomicOr(&flag, 1);
        __syncthreads();
        for (int i = t; i < SS; i += 256)
            g_maskf[i] = flag ? (msk[i] != 0 ? 1.0f : 0.0f)
                              : (((const int*)msk)[i] != 0 ? 1.0f : 0.0f);
        if (t < HH * 4) {
            float x = pw[t];
            g_spw[t] = (x > 20.0f) ? x : log1pf(expf(x));
        }
    }
    const int ROW4 = NPROJ / 4;          // 288
    const int TOT4 = CC * ROW4;          // 110592
    float4* dstW = (float4*)g_Wc;
    for (int idx = blockIdx.x * blockDim.x + threadIdx.x; idx < TOT4 + ROW4;
         idx += gridDim.x * blockDim.x) {
        if (idx < TOT4) {
            int row = idx / ROW4, r = idx % ROW4;
            const float* src;  int c4, w4;
            if      (r < 48)  { src = Wq_s; c4 = r;        w4 = 48; }
            else if (r < 96)  { src = Wk_s; c4 = r - 48;   w4 = 48; }
            else if (r < 144) { src = Wv_s; c4 = r - 96;   w4 = 48; }
            else if (r < 180) { src = Wq_p; c4 = r - 144;  w4 = 36; }
            else if (r < 216) { src = Wk_p; c4 = r - 180;  w4 = 36; }
            else              { src = Wv_p; c4 = r - 216;  w4 = 72; }
            dstW[idx] = ((const float4*)src)[row * w4 + c4];
        } else {
            int r = idx - TOT4;
            const float* src;  int c4;
            if      (r < 48)  { src = bq_s; c4 = r; }
            else if (r < 96)  { src = bk_s; c4 = r - 48; }
            else if (r < 144) { src = bv_s; c4 = r - 96; }
            else if (r < 180) { src = bq_p; c4 = r - 144; }
            else if (r < 216) { src = bk_p; c4 = r - 180; }
            else              { src = bv_p; c4 = r - 216; }
            ((float4*)g_bc)[r] = ((const float4*)src)[c4];
        }
    }
}

// ---------------- generic SGEMM (double-buffered, 256 thr, 4x4 microtile) --
__global__ void gemm64(const float* __restrict__ A, const float* __restrict__ W,
                       const float* __restrict__ bias, float* __restrict__ Cmat,
                       int M, int N, int K, const float* __restrict__ mask) {
    __shared__ __align__(16) float As[2][16][64];
    __shared__ __align__(16) float Ws[2][16][64];
    int tid = threadIdx.x;
    int tx = tid & 15, ty = tid >> 4;
    int n0 = blockIdx.x * 64, m0 = blockIdx.y * 64;

    int kkA[4], mA[4], nW[4], kkW[4];
    #pragma unroll
    for (int l = 0; l < 4; ++l) {
        int e = tid + l * 256;
        kkA[l] = e & 15;  mA[l] = e >> 4;
        nW[l]  = e & 63;  kkW[l] = e >> 6;
    }
    #pragma unroll
    for (int l = 0; l < 4; ++l) {
        As[0][kkA[l]][mA[l]] = A[(m0 + mA[l]) * K + kkA[l]];
        Ws[0][kkW[l]][nW[l]] = W[kkW[l] * N + n0 + nW[l]];
    }
    __syncthreads();

    float acc[4][4] = {};
    int nt = K >> 4;
    for (int t = 0; t < nt; ++t) {
        int cur = t & 1;
        float ar[4], wr[4];
        if (t + 1 < nt) {
            int k0n = (t + 1) << 4;
            #pragma unroll
            for (int l = 0; l < 4; ++l) {
                ar[l] = A[(m0 + mA[l]) * K + k0n + kkA[l]];
                wr[l] = W[(k0n + kkW[l]) * N + n0 + nW[l]];
            }
        }
        #pragma unroll
        for (int kk = 0; kk < 16; ++kk) {
            float4 a4 = *(const float4*)&As[cur][kk][ty * 4];
            float4 b4 = *(const float4*)&Ws[cur][kk][tx * 4];
            float av[4] = {a4.x, a4.y, a4.z, a4.w};
            float bv[4] = {b4.x, b4.y, b4.z, b4.w};
            #pragma unroll
            for (int i = 0; i < 4; ++i)
                #pragma unroll
                for (int j = 0; j < 4; ++j) acc[i][j] += av[i] * bv[j];
        }
        if (t + 1 < nt) {
            #pragma unroll
            for (int l = 0; l < 4; ++l) {
                As[cur ^ 1][kkA[l]][mA[l]] = ar[l];
                Ws[cur ^ 1][kkW[l]][nW[l]] = wr[l];
            }
        }
        __syncthreads();
    }
    #pragma unroll
    for (int i = 0; i < 4; ++i) {
        int m = m0 + ty * 4 + i;
        float sc = mask ? mask[m] : 1.0f;
        #pragma unroll
        for (int j = 0; j < 4; ++j) {
            int n = n0 + tx * 4 + j;
            Cmat[m * N + n] = (acc[i][j] + bias[n]) * sc;
        }
    }
}

// ---------------- K2: rotate points, build augmented Q̃/K̃ (dim-major) + V --
__global__ void rotate_pack(const float* __restrict__ rot, const float* __restrict__ trans) {
    int s = blockIdx.x;
    int t = threadIdx.x;                 // 128 threads
    __shared__ float pts[576];
    __shared__ float Rs[9], ts_[3];
    if (t < 9) Rs[t] = rot[s * 9 + t];
    if (t >= 16 && t < 19) ts_[t - 16] = trans[s * 3 + (t - 16)];
    const float* pr = g_proj + s * NPROJ;

    #pragma unroll
    for (int e = t; e < 576; e += 128) {
        float v = pr[e];
        int seg = e / 192, r = e % 192;
        int h = r >> 4, d = r & 15;
        if      (seg == 0) g_Qa[h * (AD * SS) + d * SS + s] = 0.25f * v;
        else if (seg == 1) g_Ka[h * (AD * SS) + d * SS + s] = v;
        else               g_Vc[(h * SS + s) * VD + d] = v;
    }
    #pragma unroll
    for (int e = t; e < 576; e += 128) pts[e] = pr[576 + e];
    __syncthreads();

    if (t < 24) {
        bool isQ = t < 12;
        int h = isQ ? t : t - 12;
        const float* p = pts + (isQ ? 0 : 144) + h * 12;
        float* base = (isQ ? g_Qa : g_Ka) + h * (AD * SS);
        float s2 = 0.0f;
        #pragma unroll
        for (int pp = 0; pp < 4; ++pp) {
            float x = p[pp * 3 + 0], y = p[pp * 3 + 1], z = p[pp * 3 + 2];
            float gx = Rs[0] * x + Rs[1] * y + Rs[2] * z + ts_[0];
            float gy = Rs[3] * x + Rs[4] * y + Rs[5] * z + ts_[1];
            float gz = Rs[6] * x + Rs[7] * y + Rs[8] * z + ts_[2];
            float w = g_spw[h * 4 + pp];
            s2 += w * (gx * gx + gy * gy + gz * gz);
            float m = isQ ? w : 1.0f;
            base[(16 + pp * 3 + 0) * SS + s] = m * gx;
            base[(16 + pp * 3 + 1) * SS + s] = m * gy;
            base[(16 + pp * 3 + 2) * SS + s] = m * gz;
        }
        base[28 * SS + s] = isQ ? -0.5f * s2 : 1.0f;
        base[29 * SS + s] = isQ ? 1.0f : -0.5f * s2;
        base[30 * SS + s] = 0.0f;
        base[31 * SS + s] = 0.0f;
    } else if (t >= 32) {
        int q = t - 32;                   // 96 v-point tasks
        const float* p = pts + 288 + q * 3;
        float* o = g_Vc + ((q >> 3) * SS + s) * VD + 16 + (q & 7) * 3;
        float x = p[0], y = p[1], z = p[2];
        o[0] = Rs[0] * x + Rs[1] * y + Rs[2] * z + ts_[0];
        o[1] = Rs[3] * x + Rs[4] * y + Rs[5] * z + ts_[1];
        o[2] = Rs[6] * x + Rs[7] * y + Rs[8] * z + ts_[2];
    }
}

// ---------------- K3a: logits[h] = Q̃ᵀ K̃ ; tile 64m x 128n, 8x4 microtile --
__global__ void logits_gemm() {
    int h = blockIdx.z;
    int n0 = blockIdx.x * 128, m0 = blockIdx.y * 64;
    __shared__ __align__(16) float Qs[AD][64];
    __shared__ __align__(16) float Ks[AD][128];
    int tid = threadIdx.x;               // 256
    const float* qb = g_Qa + h * (AD * SS);
    const float* kb = g_Ka + h * (AD * SS);
    #pragma unroll
    for (int l = 0; l < 2; ++l) {
        int idx = tid + l * 256;         // 512 float4 slots for Qs
        int k = idx >> 4, m4 = idx & 15;
        *(float4*)&Qs[k][m4 * 4] = *(const float4*)&qb[k * SS + m0 + m4 * 4];
    }
    #pragma unroll
    for (int l = 0; l < 4; ++l) {
        int idx = tid + l * 256;         // 1024 float4 slots for Ks
        int k = idx >> 5, n4 = idx & 31;
        *(float4*)&Ks[k][n4 * 4] = *(const float4*)&kb[k * SS + n0 + n4 * 4];
    }
    __syncthreads();
    int tx = tid & 31, ty = tid >> 5;    // tx: 32 col-groups, ty: 8 row-groups
    float acc[8][4] = {};
    #pragma unroll
    for (int k = 0; k < AD; ++k) {
        float4 b4 = *(const float4*)&Ks[k][tx * 4];
        float4 a0 = *(const float4*)&Qs[k][ty * 8];
        float4 a1 = *(const float4*)&Qs[k][ty * 8 + 4];
        float av[8] = {a0.x, a0.y, a0.z, a0.w, a1.x, a1.y, a1.z, a1.w};
        float bv[4] = {b4.x, b4.y, b4.z, b4.w};
        #pragma unroll
        for (int i = 0; i < 8; ++i)
            #pragma unroll
            for (int j = 0; j < 4; ++j) acc[i][j] += av[i] * bv[j];
    }
    float4 mq = ((const float4*)g_maskf)[(n0 >> 2) + tx];
    #pragma unroll
    for (int i = 0; i < 8; ++i) {
        int m = m0 + ty * 8 + i;
        float4 v;
        v.x = (mq.x != 0.0f) ? acc[i][0] : -10000.0f;
        v.y = (mq.y != 0.0f) ? acc[i][1] : -10000.0f;
        v.z = (mq.z != 0.0f) ? acc[i][2] : -10000.0f;
        v.w = (mq.w != 0.0f) ? acc[i][3] : -10000.0f;
        *(float4*)&g_attn[(h * SS + m) * SS + n0 + tx * 4] = v;
    }
}

// ---------------- K3b: softmax over rows of g_attn (warp per row) ----------
__global__ void softmax_rows() {
    int row = blockIdx.x * 8 + (threadIdx.x >> 5);   // 0 .. HH*SS-1
    int lane = threadIdx.x & 31;
    float* r = g_attn + row * SS;
    float4 v[4];
    float m = -1e30f;
    #pragma unroll
    for (int c = 0; c < 4; ++c) {
        v[c] = *(const float4*)&r[(lane + c * 32) * 4];
        m = fmaxf(m, fmaxf(fmaxf(v[c].x, v[c].y), fmaxf(v[c].z, v[c].w)));
    }
    #pragma unroll
    for (int o = 16; o; o >>= 1) m = fmaxf(m, __shfl_xor_sync(0xFFFFFFFFu, m, o));
    float sum = 0.0f;
    #pragma unroll
    for (int c = 0; c < 4; ++c) {
        v[c].x = __expf(v[c].x - m);  v[c].y = __expf(v[c].y - m);
        v[c].z = __expf(v[c].z - m);  v[c].w = __expf(v[c].w - m);
        sum += v[c].x + v[c].y + v[c].z + v[c].w;
    }
    #pragma unroll
    for (int o = 16; o; o >>= 1) sum += __shfl_xor_sync(0xFFFFFFFFu, sum, o);
    float inv = g_maskf[row & (SS - 1)] / sum;
    #pragma unroll
    for (int c = 0; c < 4; ++c) {
        v[c].x *= inv;  v[c].y *= inv;  v[c].z *= inv;  v[c].w *= inv;
        *(float4*)&r[(lane + c * 32) * 4] = v[c];
    }
}

// ---------------- K4: attn@V fused with combined-feature epilogue ----------
__global__ void attn_apply(const float* __restrict__ rot, const float* __restrict__ trans) {
    int h = blockIdx.y, i0 = blockIdx.x * 32;
    __shared__ __align__(16) float at[32][68];   // padded
    __shared__ __align__(16) float vv[64][VD];
    __shared__ __align__(16) float ot[32][44];   // out40 staging (padded)
    int tid = threadIdx.x;
    int il = tid >> 3, dg = tid & 7;   // 32 queries x 8 dim-groups (5 dims each)
    float acc[5] = {};
    for (int j0 = 0; j0 < SS; j0 += 64) {
        #pragma unroll
        for (int l = 0; l < 2; ++l) {            // 512 float4 fills of at
            int idx = tid + l * 256;
            int rr = idx >> 4, c4 = idx & 15;
            *(float4*)&at[rr][c4 * 4] =
                *(const float4*)&g_attn[(h * SS + i0 + rr) * SS + j0 + c4 * 4];
        }
        #pragma unroll
        for (int l = 0; l < 3; ++l) {            // 640 float4 fills of vv
            int idx = tid + l * 256;
            if (idx < 640) {
                int rr = idx / 10, c4 = idx % 10;
                *(float4*)&vv[rr][c4 * 4] =
                    ((const float4*)(g_Vc + (h * SS + j0 + rr) * VD))[c4];
            }
        }
        __syncthreads();
        #pragma unroll 8
        for (int jj = 0; jj < 64; ++jj) {
            float a = at[il][jj];
            #pragma unroll
            for (int q = 0; q < 5; ++q) acc[q] += a * vv[jj][dg * 5 + q];
        }
        __syncthreads();
    }
    #pragma unroll
    for (int q = 0; q < 5; ++q) ot[il][dg * 5 + q] = acc[q];
    __syncthreads();

    // epilogue: scalar copies (512 tasks -> 2 per thread)
    #pragma unroll
    for (int l = 0; l < 2; ++l) {
        int e = tid + l * 256;
        int q = e >> 4, d = e & 15;              // query, scalar dim
        g_comb[(i0 + q) * COMB + h * 16 + d] = ot[q][d];
    }
    // epilogue: point tasks (32 queries x 8 points = 256, one per thread)
    {
        int q = tid >> 3, p = tid & 7;
        int s = i0 + q;
        float v0 = ot[q][16 + 3 * p + 0] - trans[s * 3 + 0];
        float v1 = ot[q][16 + 3 * p + 1] - trans[s * 3 + 1];
        float v2 = ot[q][16 + 3 * p + 2] - trans[s * 3 + 2];
        const float* R = rot + s * 9;
        float p0 = R[0] * v0 + R[3] * v1 + R[6] * v2;   // R^T v
        float p1 = R[1] * v0 + R[4] * v1 + R[7] * v2;
        float p2 = R[2] * v0 + R[5] * v1 + R[8] * v2;
        float* cb = g_comb + s * COMB;
        cb[192 + (h * 8 + p) * 3 + 0] = p0;
        cb[192 + (h * 8 + p) * 3 + 1] = p1;
        cb[192 + (h * 8 + p) * 3 + 2] = p2;
        cb[480 + h * 8 + p] = sqrtf(p0 * p0 + p1 * p1 + p2 * p2);
    }
}

// ---------------------------------------------------------------------------
extern "C" void kernel_launch(void* const* d_in, const int* in_sizes, int n_in,
                              void* d_out, int out_size) {
    const float* single = (const float*)d_in[0];
    const float* rot    = (const float*)d_in[1];
    const float* trans  = (const float*)d_in[2];
    const float* Wq_s = (const float*)d_in[3];  const float* bq_s = (const float*)d_in[4];
    const float* Wk_s = (const float*)d_in[5];  const float* bk_s = (const float*)d_in[6];
    const float* Wv_s = (const float*)d_in[7];  const float* bv_s = (const float*)d_in[8];
    const float* Wq_p = (const float*)d_in[9];  const float* bq_p = (const float*)d_in[10];
    const float* Wk_p = (const float*)d_in[11]; const float* bk_p = (const float*)d_in[12];
    const float* Wv_p = (const float*)d_in[13]; const float* bv_p = (const float*)d_in[14];
    const float* pw   = (const float*)d_in[15];
    const float* Wo   = (const float*)d_in[16];
    const float* bo   = (const float*)d_in[17];
    const unsigned char* mask = (const unsigned char*)d_in[18];
    float* out = (float*)d_out;

    float *pWc, *pbc, *pproj, *pcomb, *pmaskf;
    cudaGetSymbolAddress((void**)&pWc,    g_Wc);
    cudaGetSymbolAddress((void**)&pbc,    g_bc);
    cudaGetSymbolAddress((void**)&pproj,  g_proj);
    cudaGetSymbolAddress((void**)&pcomb,  g_comb);
    cudaGetSymbolAddress((void**)&pmaskf, g_maskf);

    pack_weights<<<432, 256>>>(Wq_s, Wk_s, Wv_s, Wq_p, Wk_p, Wv_p,
                               bq_s, bk_s, bv_s, bq_p, bk_p, bv_p, pw, mask);
    gemm64<<<dim3(NPROJ / 64, SS / 64), 256>>>(single, pWc, pbc, pproj,
                                               SS, NPROJ, CC, (const float*)0);
    rotate_pack<<<SS, 128>>>(rot, trans);
    logits_gemm<<<dim3(SS / 128, SS / 64, HH), 256>>>();
    softmax_rows<<<HH * SS / 8, 256>>>();
    attn_apply<<<dim3(SS / 32, HH), 256>>>(rot, trans);
    gemm64<<<dim3(CC / 64, SS / 64), 256>>>(pcomb, Wo, bo, out, SS, CC, COMB, pmaskf);
}